// round 4
// baseline (speedup 1.0000x reference)
#include <cuda_runtime.h>
#include <math.h>

#define BB 2
#define TT 2048
#define DD 1024
#define HH 16
#define DH 64
#define M_TOT (BB*TT)   // 4096

// ---------------- scratch (static device arrays; no allocations) ----------------
__device__ float g_Q[BB*HH*TT*DH];      // [B,H,T,dh] 16 MB
__device__ float g_K[BB*HH*TT*DH];
__device__ float g_V[BB*HH*TT*DH];
__device__ float g_proj[M_TOT*256];     // [m][4*64]: w1w|w2w|w1r|w2r
__device__ float g_rd[M_TOT*HH*6];      // normalized read lines
__device__ float g_wj[M_TOT*HH*6];      // normalized write lines, J-applied
__device__ float g_dp[HH*TT];           // decay^t
__device__ float g_dn[HH*TT];           // decay^-t
__device__ float g_ctx[M_TOT*DD];       // attention output [B,T,D]

// ---------------- GEMM: qkv projection ----------------
// C = x[4096,1024] @ w_qkv[3072,1024]^T + b ; scatter to Q/K/V [B,H,T,dh]
__global__ __launch_bounds__(256) void k_gemm_qkv(const float* __restrict__ A,
                                                  const float* __restrict__ W,
                                                  const float* __restrict__ bias) {
    __shared__ float As[16][68];
    __shared__ float Bs[16][68];
    const int Kd = DD;
    int m0 = blockIdx.y * 64, n0 = blockIdx.x * 64;
    int tid = threadIdx.x;
    int tx = tid & 15, ty = tid >> 4;
    int r = tid >> 2, c4 = tid & 3;
    float acc[4][4] = {};
    for (int k0 = 0; k0 < Kd; k0 += 16) {
        float4 av = *(const float4*)&A[(m0 + r)*Kd + k0 + c4*4];
        float4 bv = *(const float4*)&W[(n0 + r)*Kd + k0 + c4*4];
        As[c4*4+0][r]=av.x; As[c4*4+1][r]=av.y; As[c4*4+2][r]=av.z; As[c4*4+3][r]=av.w;
        Bs[c4*4+0][r]=bv.x; Bs[c4*4+1][r]=bv.y; Bs[c4*4+2][r]=bv.z; Bs[c4*4+3][r]=bv.w;
        __syncthreads();
        #pragma unroll
        for (int kk = 0; kk < 16; kk++) {
            float4 a = *(const float4*)&As[kk][ty*4];
            float4 b = *(const float4*)&Bs[kk][tx*4];
            float ar[4] = {a.x,a.y,a.z,a.w};
            float br[4] = {b.x,b.y,b.z,b.w};
            #pragma unroll
            for (int i=0;i<4;i++)
                #pragma unroll
                for (int j=0;j<4;j++)
                    acc[i][j] += ar[i]*br[j];
        }
        __syncthreads();
    }
    #pragma unroll
    for (int i=0;i<4;i++){
        int m = m0 + ty*4 + i;
        int b = m >> 11, t = m & (TT-1);
        #pragma unroll
        for (int j=0;j<4;j++){
            int n = n0 + tx*4 + j;
            float v = acc[i][j] + bias[n];
            int c = n >> 10, hd = n & 1023;
            int h = hd >> 6, d = hd & 63;
            float* dst = (c==0) ? g_Q : (c==1) ? g_K : g_V;
            dst[(((b*HH + h)*TT + t)*DH) + d] = v;
        }
    }
}

// ---------------- GEMM: line projections (N=256, four 64-row weights) ----------------
__global__ __launch_bounds__(256) void k_gemm_proj(const float* __restrict__ A,
        const float* __restrict__ W0, const float* __restrict__ W1,
        const float* __restrict__ W2, const float* __restrict__ W3) {
    __shared__ float As[16][68];
    __shared__ float Bs[16][68];
    const int Kd = DD;
    const float* W = (blockIdx.x==0) ? W0 : (blockIdx.x==1) ? W1 : (blockIdx.x==2) ? W2 : W3;
    int m0 = blockIdx.y * 64, n0 = blockIdx.x * 64;
    int tid = threadIdx.x;
    int tx = tid & 15, ty = tid >> 4;
    int r = tid >> 2, c4 = tid & 3;
    float acc[4][4] = {};
    for (int k0 = 0; k0 < Kd; k0 += 16) {
        float4 av = *(const float4*)&A[(m0 + r)*Kd + k0 + c4*4];
        float4 bv = *(const float4*)&W[r*Kd + k0 + c4*4];
        As[c4*4+0][r]=av.x; As[c4*4+1][r]=av.y; As[c4*4+2][r]=av.z; As[c4*4+3][r]=av.w;
        Bs[c4*4+0][r]=bv.x; Bs[c4*4+1][r]=bv.y; Bs[c4*4+2][r]=bv.z; Bs[c4*4+3][r]=bv.w;
        __syncthreads();
        #pragma unroll
        for (int kk = 0; kk < 16; kk++) {
            float4 a = *(const float4*)&As[kk][ty*4];
            float4 b = *(const float4*)&Bs[kk][tx*4];
            float ar[4] = {a.x,a.y,a.z,a.w};
            float br[4] = {b.x,b.y,b.z,b.w};
            #pragma unroll
            for (int i=0;i<4;i++)
                #pragma unroll
                for (int j=0;j<4;j++)
                    acc[i][j] += ar[i]*br[j];
        }
        __syncthreads();
    }
    #pragma unroll
    for (int i=0;i<4;i++){
        int m = m0 + ty*4 + i;
        #pragma unroll
        for (int j=0;j<4;j++){
            int n = n0 + tx*4 + j;
            g_proj[m*256 + n] = acc[i][j];
        }
    }
}

// ---------------- GEMM: output projection ----------------
__global__ __launch_bounds__(256) void k_gemm_out(const float* __restrict__ W,
                                                  const float* __restrict__ bias,
                                                  float* __restrict__ out) {
    __shared__ float As[16][68];
    __shared__ float Bs[16][68];
    const int Kd = DD;
    int m0 = blockIdx.y * 64, n0 = blockIdx.x * 64;
    int tid = threadIdx.x;
    int tx = tid & 15, ty = tid >> 4;
    int r = tid >> 2, c4 = tid & 3;
    float acc[4][4] = {};
    for (int k0 = 0; k0 < Kd; k0 += 16) {
        float4 av = *(const float4*)&g_ctx[(m0 + r)*Kd + k0 + c4*4];
        float4 bv = *(const float4*)&W[(n0 + r)*Kd + k0 + c4*4];
        As[c4*4+0][r]=av.x; As[c4*4+1][r]=av.y; As[c4*4+2][r]=av.z; As[c4*4+3][r]=av.w;
        Bs[c4*4+0][r]=bv.x; Bs[c4*4+1][r]=bv.y; Bs[c4*4+2][r]=bv.z; Bs[c4*4+3][r]=bv.w;
        __syncthreads();
        #pragma unroll
        for (int kk = 0; kk < 16; kk++) {
            float4 a = *(const float4*)&As[kk][ty*4];
            float4 b = *(const float4*)&Bs[kk][tx*4];
            float ar[4] = {a.x,a.y,a.z,a.w};
            float br[4] = {b.x,b.y,b.z,b.w};
            #pragma unroll
            for (int i=0;i<4;i++)
                #pragma unroll
                for (int j=0;j<4;j++)
                    acc[i][j] += ar[i]*br[j];
        }
        __syncthreads();
    }
    #pragma unroll
    for (int i=0;i<4;i++){
        int m = m0 + ty*4 + i;
        #pragma unroll
        for (int j=0;j<4;j++){
            int n = n0 + tx*4 + j;
            out[m*DD + n] = acc[i][j] + bias[n];
        }
    }
}

// ---------------- decay tables ----------------
__global__ void k_tables(const float* __restrict__ decay_logits) {
    int idx = blockIdx.x*blockDim.x + threadIdx.x;
    if (idx >= HH*TT) return;
    int h = idx / TT, t = idx % TT;
    float dec = 1.f / (1.f + expf(-decay_logits[h]));
    float ld = logf(dec);
    g_dp[idx] = expf((float)t * ld);
    g_dn[idx] = expf(-(float)t * ld);
}

// ---------------- Plucker lines (exterior product, normalize, J-map for write) ----------------
__global__ void k_lines() {
    int idx = blockIdx.x*blockDim.x + threadIdx.x;
    if (idx >= M_TOT*HH) return;
    int h = idx & 15;
    int m = idx >> 4;
    int t = m & (TT-1);
    const float* pm = &g_proj[m*256];
    float w1[4], w2[4], r1[4], r2[4];
    #pragma unroll
    for (int p=0;p<4;p++){
        w1[p] = (t==0) ? 0.f : g_proj[(m-1)*256 + 0*64 + h*4 + p];
        w2[p] = pm[1*64 + h*4 + p];
        r1[p] = pm[2*64 + h*4 + p];
        r2[p] = pm[3*64 + h*4 + p];
    }
    const int PI[6] = {0,0,0,1,1,2};
    const int PJ[6] = {1,2,3,2,3,3};
    float Lw[6], Lr[6];
    float sw = 0.f, sr = 0.f;
    #pragma unroll
    for (int i=0;i<6;i++){
        Lw[i] = w1[PI[i]]*w2[PJ[i]] - w1[PJ[i]]*w2[PI[i]];
        Lr[i] = r1[PI[i]]*r2[PJ[i]] - r1[PJ[i]]*r2[PI[i]];
        sw += Lw[i]*Lw[i];
        sr += Lr[i]*Lr[i];
    }
    float iw = 1.f / fmaxf(sqrtf(sw), 1e-12f);
    float ir = 1.f / fmaxf(sqrtf(sr), 1e-12f);
    float* wjb = &g_wj[(m*HH + h)*6];
    float* rdb = &g_rd[(m*HH + h)*6];
    // (L @ J6) = [L5, -L4, L3, L2, -L1, L0]
    wjb[0] =  Lw[5]*iw; wjb[1] = -Lw[4]*iw; wjb[2] =  Lw[3]*iw;
    wjb[3] =  Lw[2]*iw; wjb[4] = -Lw[1]*iw; wjb[5] =  Lw[0]*iw;
    #pragma unroll
    for (int i=0;i<6;i++) rdb[i] = Lr[i]*ir;
}

// ---------------- flash attention with incidence bias ----------------
// one thread per query row; online softmax entirely thread-local.
__global__ __launch_bounds__(128) void k_flash(const float* __restrict__ bias_scale) {
    __shared__ float Ksm[64][64];
    __shared__ float Vsm[64][64];
    __shared__ float wjs[64][6];
    __shared__ float dns[64];
    int b = blockIdx.z, h = blockIdx.y;
    int tid = threadIdx.x;
    int qt = blockIdx.x*128 + tid;

    const float* Qb = &g_Q[((b*HH + h)*TT + qt)*DH];
    float4 q4[16];
    #pragma unroll
    for (int i=0;i<16;i++) q4[i] = ((const float4*)Qb)[i];
    float rdv[6];
    #pragma unroll
    for (int j=0;j<6;j++) rdv[j] = g_rd[((b*TT + qt)*HH + h)*6 + j];
    float dpq = g_dp[h*TT + qt];
    float bsc = bias_scale[h];

    float m = -INFINITY, l = 0.f;
    float4 o4[16];
    #pragma unroll
    for (int i=0;i<16;i++) o4[i] = make_float4(0.f,0.f,0.f,0.f);

    const float scale = 0.125f;  // dh^-0.5 = 64^-0.5
    int ntiles = (blockIdx.x + 1) * 2;

    for (int kt = 0; kt < ntiles; kt++) {
        int k0 = kt*64;
        const float4* Ksrc = (const float4*)&g_K[((b*HH + h)*TT + k0)*DH];
        const float4* Vsrc = (const float4*)&g_V[((b*HH + h)*TT + k0)*DH];
        float4* Kd4 = (float4*)Ksm;
        float4* Vd4 = (float4*)Vsm;
        #pragma unroll
        for (int j=0;j<8;j++){ Kd4[tid + j*128] = Ksrc[tid + j*128]; Vd4[tid + j*128] = Vsrc[tid + j*128]; }
        for (int idx = tid; idx < 384; idx += 128)
            ((float*)wjs)[idx] = g_wj[((b*TT + k0 + idx/6)*HH + h)*6 + (idx % 6)];
        if (tid < 64) dns[tid] = g_dn[h*TT + k0 + tid];
        __syncthreads();

        #pragma unroll 1
        for (int c = 0; c < 4; c++) {
            float s[16];
            float mloc = -INFINITY;
            #pragma unroll
            for (int kk=0; kk<16; kk++) {
                int krow = c*16 + kk;
                int k = k0 + krow;
                float sv;
                if (k > qt) {
                    sv = -INFINITY;
                } else {
                    float acc = 0.f;
                    const float4* kr = (const float4*)&Ksm[krow][0];
                    #pragma unroll
                    for (int d=0; d<16; d++){
                        float4 kv = kr[d];
                        acc += q4[d].x*kv.x + q4[d].y*kv.y + q4[d].z*kv.z + q4[d].w*kv.w;
                    }
                    sv = acc * scale;
                    if (k < qt) {
                        float inc = rdv[0]*wjs[krow][0] + rdv[1]*wjs[krow][1] + rdv[2]*wjs[krow][2]
                                  + rdv[3]*wjs[krow][3] + rdv[4]*wjs[krow][4] + rdv[5]*wjs[krow][5];
                        sv += inc * bsc * dpq * dns[krow];
                    }
                }
                s[kk] = sv;
                mloc = fmaxf(mloc, sv);
            }
            float mnew = fmaxf(m, mloc);
            if (mnew == -INFINITY) continue;   // whole-prefix masked (safety; unreachable)
            float alpha = __expf(m - mnew);
            l *= alpha;
            #pragma unroll
            for (int kk=0; kk<16; kk++){
                float p = __expf(s[kk] - mnew);
                s[kk] = p;
                l += p;
            }
            m = mnew;
            #pragma unroll
            for (int d=0; d<16; d++){
                float4 acc = o4[d];
                acc.x*=alpha; acc.y*=alpha; acc.z*=alpha; acc.w*=alpha;
                #pragma unroll
                for (int kk=0; kk<16; kk++){
                    float p = s[kk];
                    float4 vv = ((const float4*)&Vsm[c*16+kk][0])[d];
                    acc.x += p*vv.x; acc.y += p*vv.y; acc.z += p*vv.z; acc.w += p*vv.w;
                }
                o4[d] = acc;
            }
        }
        __syncthreads();
    }

    float inv = 1.f / l;
    float* outp = &g_ctx[(b*TT + qt)*DD + h*DH];
    #pragma unroll
    for (int d=0; d<16; d++){
        float4 ov = o4[d];
        ov.x*=inv; ov.y*=inv; ov.z*=inv; ov.w*=inv;
        ((float4*)outp)[d] = ov;
    }
}

// ---------------- launch ----------------
extern "C" void kernel_launch(void* const* d_in, const int* in_sizes, int n_in,
                              void* d_out, int out_size) {
    const float* x      = (const float*)d_in[0];
    const float* w_qkv  = (const float*)d_in[1];
    const float* b_qkv  = (const float*)d_in[2];
    const float* w1w    = (const float*)d_in[3];
    const float* w2w    = (const float*)d_in[4];
    const float* w1r    = (const float*)d_in[5];
    const float* w2r    = (const float*)d_in[6];
    const float* w_out  = (const float*)d_in[7];
    const float* b_out  = (const float*)d_in[8];
    const float* dl     = (const float*)d_in[9];
    const float* bs     = (const float*)d_in[10];
    float* out = (float*)d_out;

    k_gemm_qkv<<<dim3(48, 64), 256>>>(x, w_qkv, b_qkv);
    k_gemm_proj<<<dim3(4, 64), 256>>>(x, w1w, w2w, w1r, w2r);
    k_tables<<<(HH*TT + 255)/256, 256>>>(dl);
    k_lines<<<(M_TOT*HH + 255)/256, 256>>>();
    k_flash<<<dim3(TT/128, HH, BB), 128>>>(bs);
    k_gemm_out<<<dim3(16, 64), 256>>>(w_out, b_out, out);
}

// round 11
// speedup vs baseline: 1.4831x; 1.4831x over previous
#include <cuda_runtime.h>
#include <cuda_bf16.h>
#include <math.h>
#include <stdint.h>

#define BB 2
#define TT 2048
#define DD 1024
#define HH 16
#define DH 64
#define M_TOT (BB*TT)   // 4096

// ---------------- scratch (static device arrays; no allocations) ----------------
__device__ __nv_bfloat16 g_xh[M_TOT*DD];        // x split-bf16
__device__ __nv_bfloat16 g_xl[M_TOT*DD];
__device__ __nv_bfloat16 g_wqkvh[3*DD*DD];
__device__ __nv_bfloat16 g_wqkvl[3*DD*DD];
__device__ __nv_bfloat16 g_wph[256*DD];         // concat w1w|w2w|w1r|w2r
__device__ __nv_bfloat16 g_wpl[256*DD];
__device__ __nv_bfloat16 g_woh[DD*DD];
__device__ __nv_bfloat16 g_wol[DD*DD];
__device__ __nv_bfloat16 g_ctxh[M_TOT*DD];      // attention output, split-bf16
__device__ __nv_bfloat16 g_ctxl[M_TOT*DD];
__device__ float g_qkv[M_TOT*3*DD];             // [m][3072]: q|k|v rows
__device__ float g_proj[M_TOT*256];             // [m][4*64]: w1w|w2w|w1r|w2r
__device__ float g_rd[M_TOT*HH*6];              // normalized read lines
__device__ float g_wj[M_TOT*HH*6];              // normalized write lines, J-applied
__device__ float g_dp[HH*TT];                   // decay^t
__device__ float g_dn[HH*TT];                   // decay^-t

// ---------------- helpers ----------------
__device__ __forceinline__ uint32_t smem_u32(const void* p){
    uint32_t a;
    asm("{ .reg .u64 t; cvta.to.shared.u64 t, %1; cvt.u32.u64 %0, t; }":"=r"(a):"l"(p));
    return a;
}
__device__ __forceinline__ void ldm4(uint32_t* r, uint32_t a){
    asm volatile("ldmatrix.sync.aligned.m8n8.x4.shared.b16 {%0,%1,%2,%3}, [%4];"
        : "=r"(r[0]),"=r"(r[1]),"=r"(r[2]),"=r"(r[3]) : "r"(a));
}
__device__ __forceinline__ void mma16816(float* d, const uint32_t* a, const uint32_t* b){
    asm volatile("mma.sync.aligned.m16n8k16.row.col.f32.bf16.bf16.f32 "
        "{%0,%1,%2,%3}, {%4,%5,%6,%7}, {%8,%9}, {%0,%1,%2,%3};"
        : "+f"(d[0]),"+f"(d[1]),"+f"(d[2]),"+f"(d[3])
        : "r"(a[0]),"r"(a[1]),"r"(a[2]),"r"(a[3]),"r"(b[0]),"r"(b[1]));
}

// ---------------- split-bf16 conversion ----------------
__global__ void k_conv(const float* __restrict__ s, int n4, int mode, int off4){
    int i = blockIdx.x*blockDim.x + threadIdx.x;
    if (i >= n4) return;
    float4 v = ((const float4*)s)[i];
    __nv_bfloat16 h0 = __float2bfloat16_rn(v.x), h1 = __float2bfloat16_rn(v.y);
    __nv_bfloat16 h2 = __float2bfloat16_rn(v.z), h3 = __float2bfloat16_rn(v.w);
    __nv_bfloat16 l0 = __float2bfloat16_rn(v.x - __bfloat162float(h0));
    __nv_bfloat16 l1 = __float2bfloat16_rn(v.y - __bfloat162float(h1));
    __nv_bfloat16 l2 = __float2bfloat16_rn(v.z - __bfloat162float(h2));
    __nv_bfloat16 l3 = __float2bfloat16_rn(v.w - __bfloat162float(h3));
    __nv_bfloat16 *hp, *lp;
    if      (mode == 0) { hp = g_xh;    lp = g_xl;    }
    else if (mode == 1) { hp = g_wqkvh; lp = g_wqkvl; }
    else if (mode == 2) { hp = g_wph;   lp = g_wpl;   }
    else                { hp = g_woh;   lp = g_wol;   }
    int o = (off4 + i) * 2;
    ((__nv_bfloat162*)hp)[o  ] = __halves2bfloat162(h0, h1);
    ((__nv_bfloat162*)hp)[o+1] = __halves2bfloat162(h2, h3);
    ((__nv_bfloat162*)lp)[o  ] = __halves2bfloat162(l0, l1);
    ((__nv_bfloat162*)lp)[o+1] = __halves2bfloat162(l2, l3);
}

// ---------------- mma.sync GEMM: C[M,N] = A[M,K] @ B[N,K]^T (+bias) ----------------
// split-bf16: C = Ah*Bh + Ah*Bl + Al*Bh, fp32 accumulate in registers.
// CTA tile 128x128, 8 warps (2x4), warp tile 64x32. K panels of 64 bf16,
// double-buffered via cp.async. smem panel layout: 128 rows x 128B, swizzle<3,4,3>.
#define PBUF 65536
#define GSM_TOT (2*PBUF)

__device__ __forceinline__ void panel_load(uint32_t sb, int bufi, int k0, int tid,
        const __nv_bfloat16* Ah, const __nv_bfloat16* Al,
        const __nv_bfloat16* Bh, const __nv_bfloat16* Bl, int m0, int n0){
    #pragma unroll
    for (int i = 0; i < 16; i++){
        int flat = i*256 + tid;
        int sel = flat >> 10, idx = flat & 1023;
        int row = idx >> 3, ch = idx & 7;
        const __nv_bfloat16* s; int rg; uint32_t off;
        if      (sel == 0){ s = Ah; rg = m0 + row; off = 0;     }
        else if (sel == 1){ s = Al; rg = m0 + row; off = 16384; }
        else if (sel == 2){ s = Bh; rg = n0 + row; off = 32768; }
        else              { s = Bl; rg = n0 + row; off = 49152; }
        uint32_t byt = (uint32_t)(row*128 + ch*16);
        byt ^= (byt >> 3) & 0x70;
        uint32_t dst = sb + (uint32_t)bufi*PBUF + off + byt;
        const void* src = s + (size_t)rg*DD + k0 + ch*8;
        asm volatile("cp.async.cg.shared.global [%0], [%1], 16;" :: "r"(dst), "l"(src) : "memory");
    }
    asm volatile("cp.async.commit_group;" ::: "memory");
}

__global__ __launch_bounds__(256, 1) void k_mmagemm(int mode, const float* __restrict__ bias,
                                                    float* __restrict__ outp){
    extern __shared__ __align__(1024) char smem[];
    const __nv_bfloat16 *Ah, *Al, *Bh, *Bl;
    float* C; int ldc;
    if (mode == 0){ Ah=g_xh;   Al=g_xl;   Bh=g_wqkvh; Bl=g_wqkvl; C=g_qkv;  ldc=3072; }
    else if (mode == 1){ Ah=g_xh; Al=g_xl; Bh=g_wph; Bl=g_wpl;    C=g_proj; ldc=256;  }
    else { Ah=g_ctxh; Al=g_ctxl; Bh=g_woh; Bl=g_wol;              C=outp;   ldc=1024; }

    uint32_t sb = smem_u32(smem);
    int tid = threadIdx.x, wid = tid >> 5, lane = tid & 31;
    int m0 = blockIdx.y * 128, n0 = blockIdx.x * 128;
    int wm = wid >> 2, wn = wid & 3;           // 2 x 4 warp grid

    float acc[4][4][4];
    #pragma unroll
    for (int a=0;a<4;a++)
        #pragma unroll
        for (int b=0;b<4;b++)
            #pragma unroll
            for (int c=0;c<4;c++) acc[a][b][c] = 0.f;

    panel_load(sb, 0, 0, tid, Ah, Al, Bh, Bl, m0, n0);

    for (int p = 0; p < 16; p++){
        if (p < 15){
            panel_load(sb, (p+1)&1, (p+1)*64, tid, Ah, Al, Bh, Bl, m0, n0);
            asm volatile("cp.async.wait_group 1;" ::: "memory");
        } else {
            asm volatile("cp.async.wait_group 0;" ::: "memory");
        }
        __syncthreads();
        uint32_t base = sb + (uint32_t)(p&1)*PBUF;

        #pragma unroll
        for (int ks = 0; ks < 4; ks++){
            uint32_t ahf[4][4], alf[4][4], bhf[4][2], blf[4][2];
            int arl = lane & 15;
            int acb = ks*32 + ((lane >> 4) << 4);
            #pragma unroll
            for (int mt = 0; mt < 4; mt++){
                uint32_t byt = (uint32_t)((wm*64 + mt*16 + arl)*128 + acb);
                byt ^= (byt >> 3) & 0x70;
                ldm4(ahf[mt], base + byt);
                ldm4(alf[mt], base + 16384 + byt);
            }
            int brl = (lane & 7) + ((lane >> 4) & 1)*8;
            int bcb = ks*32 + ((lane >> 3) & 1)*16;
            #pragma unroll
            for (int pr = 0; pr < 2; pr++){
                uint32_t byt = (uint32_t)((wn*32 + pr*16 + brl)*128 + bcb);
                byt ^= (byt >> 3) & 0x70;
                uint32_t t[4];
                ldm4(t, base + 32768 + byt);
                bhf[pr*2][0]=t[0]; bhf[pr*2][1]=t[1]; bhf[pr*2+1][0]=t[2]; bhf[pr*2+1][1]=t[3];
                ldm4(t, base + 49152 + byt);
                blf[pr*2][0]=t[0]; blf[pr*2][1]=t[1]; blf[pr*2+1][0]=t[2]; blf[pr*2+1][1]=t[3];
            }
            #pragma unroll
            for (int mt = 0; mt < 4; mt++)
                #pragma unroll
                for (int nt = 0; nt < 4; nt++){
                    mma16816(acc[mt][nt], ahf[mt], bhf[nt]);
                    mma16816(acc[mt][nt], ahf[mt], blf[nt]);
                    mma16816(acc[mt][nt], alf[mt], bhf[nt]);
                }
        }
        __syncthreads();
    }

    // epilogue: d0,d1 -> (row, col..col+1); d2,d3 -> (row+8, col..col+1)
    int mrow  = m0 + wm*64 + (lane >> 2);
    int ncol0 = n0 + wn*32 + (lane & 3)*2;
    #pragma unroll
    for (int mt = 0; mt < 4; mt++){
        #pragma unroll
        for (int nt = 0; nt < 4; nt++){
            int n = ncol0 + nt*8;
            float bx = bias ? bias[n]   : 0.f;
            float by = bias ? bias[n+1] : 0.f;
            float2 v0 = { acc[mt][nt][0] + bx, acc[mt][nt][1] + by };
            float2 v1 = { acc[mt][nt][2] + bx, acc[mt][nt][3] + by };
            *(float2*)&C[(size_t)(mrow + mt*16    )*ldc + n] = v0;
            *(float2*)&C[(size_t)(mrow + mt*16 + 8)*ldc + n] = v1;
        }
    }
}

// ---------------- decay tables ----------------
__global__ void k_tables(const float* __restrict__ decay_logits) {
    int idx = blockIdx.x*blockDim.x + threadIdx.x;
    if (idx >= HH*TT) return;
    int h = idx / TT, t = idx % TT;
    float dec = 1.f / (1.f + expf(-decay_logits[h]));
    float ld = logf(dec);
    g_dp[idx] = expf((float)t * ld);
    g_dn[idx] = expf(-(float)t * ld);
}

// ---------------- Plucker lines ----------------
__global__ void k_lines() {
    int idx = blockIdx.x*blockDim.x + threadIdx.x;
    if (idx >= M_TOT*HH) return;
    int h = idx & 15;
    int m = idx >> 4;
    int t = m & (TT-1);
    const float* pm = &g_proj[m*256];
    float w1[4], w2[4], r1[4], r2[4];
    #pragma unroll
    for (int p=0;p<4;p++){
        w1[p] = (t==0) ? 0.f : g_proj[(m-1)*256 + 0*64 + h*4 + p];
        w2[p] = pm[1*64 + h*4 + p];
        r1[p] = pm[2*64 + h*4 + p];
        r2[p] = pm[3*64 + h*4 + p];
    }
    const int PI[6] = {0,0,0,1,1,2};
    const int PJ[6] = {1,2,3,2,3,3};
    float Lw[6], Lr[6];
    float sw = 0.f, sr = 0.f;
    #pragma unroll
    for (int i=0;i<6;i++){
        Lw[i] = w1[PI[i]]*w2[PJ[i]] - w1[PJ[i]]*w2[PI[i]];
        Lr[i] = r1[PI[i]]*r2[PJ[i]] - r1[PJ[i]]*r2[PI[i]];
        sw += Lw[i]*Lw[i];
        sr += Lr[i]*Lr[i];
    }
    float iw = 1.f / fmaxf(sqrtf(sw), 1e-12f);
    float ir = 1.f / fmaxf(sqrtf(sr), 1e-12f);
    float* wjb = &g_wj[(m*HH + h)*6];
    float* rdb = &g_rd[(m*HH + h)*6];
    wjb[0] =  Lw[5]*iw; wjb[1] = -Lw[4]*iw; wjb[2] =  Lw[3]*iw;
    wjb[3] =  Lw[2]*iw; wjb[4] = -Lw[1]*iw; wjb[5] =  Lw[0]*iw;
    #pragma unroll
    for (int i=0;i<6;i++) rdb[i] = Lr[i]*ir;
}

// ---------------- flash attention with incidence bias ----------------
__global__ __launch_bounds__(128) void k_flash(const float* __restrict__ bias_scale) {
    __shared__ float Ksm[64][64];
    __shared__ float Vsm[64][64];
    __shared__ float wjs[64][6];
    __shared__ float dns[64];
    int b = blockIdx.z, h = blockIdx.y;
    int tid = threadIdx.x;
    int qt = blockIdx.x*128 + tid;

    const float* Qb = g_qkv + (size_t)(b*TT + qt)*3072 + h*64;
    float4 q4[16];
    #pragma unroll
    for (int i=0;i<16;i++) q4[i] = ((const float4*)Qb)[i];
    float rdv[6];
    #pragma unroll
    for (int j=0;j<6;j++) rdv[j] = g_rd[((b*TT + qt)*HH + h)*6 + j];
    float dpq = g_dp[h*TT + qt];
    float bsc = bias_scale[h];

    float m = -INFINITY, l = 0.f;
    float4 o4[16];
    #pragma unroll
    for (int i=0;i<16;i++) o4[i] = make_float4(0.f,0.f,0.f,0.f);

    const float scale = 0.125f;
    int ntiles = (blockIdx.x + 1) * 2;

    for (int kt = 0; kt < ntiles; kt++) {
        int k0 = kt*64;
        float4* Kd4 = (float4*)Ksm;
        float4* Vd4 = (float4*)Vsm;
        #pragma unroll
        for (int j=0;j<8;j++){
            int idx = tid + j*128;
            int row = idx >> 4, c4 = idx & 15;
            const float4* Ks = (const float4*)(g_qkv + (size_t)(b*TT + k0 + row)*3072 + 1024 + h*64);
            const float4* Vs = (const float4*)(g_qkv + (size_t)(b*TT + k0 + row)*3072 + 2048 + h*64);
            Kd4[idx] = Ks[c4];
            Vd4[idx] = Vs[c4];
        }
        for (int idx = tid; idx < 384; idx += 128)
            ((float*)wjs)[idx] = g_wj[((b*TT + k0 + idx/6)*HH + h)*6 + (idx % 6)];
        if (tid < 64) dns[tid] = g_dn[h*TT + k0 + tid];
        __syncthreads();

        #pragma unroll 1
        for (int c = 0; c < 4; c++) {
            float s[16];
            float mloc = -INFINITY;
            #pragma unroll
            for (int kk=0; kk<16; kk++) {
                int krow = c*16 + kk;
                int k = k0 + krow;
                float sv;
                if (k > qt) {
                    sv = -INFINITY;
                } else {
                    float acc = 0.f;
                    const float4* kr = (const float4*)&Ksm[krow][0];
                    #pragma unroll
                    for (int d=0; d<16; d++){
                        float4 kv = kr[d];
                        acc += q4[d].x*kv.x + q4[d].y*kv.y + q4[d].z*kv.z + q4[d].w*kv.w;
                    }
                    sv = acc * scale;
                    if (k < qt) {
                        float inc = rdv[0]*wjs[krow][0] + rdv[1]*wjs[krow][1] + rdv[2]*wjs[krow][2]
                                  + rdv[3]*wjs[krow][3] + rdv[4]*wjs[krow][4] + rdv[5]*wjs[krow][5];
                        sv += inc * bsc * dpq * dns[krow];
                    }
                }
                s[kk] = sv;
                mloc = fmaxf(mloc, sv);
            }
            float mnew = fmaxf(m, mloc);
            if (mnew == -INFINITY) continue;
            float alpha = __expf(m - mnew);
            l *= alpha;
            #pragma unroll
            for (int kk=0; kk<16; kk++){
                float p = __expf(s[kk] - mnew);
                s[kk] = p;
                l += p;
            }
            m = mnew;
            #pragma unroll
            for (int d=0; d<16; d++){
                float4 acc = o4[d];
                acc.x*=alpha; acc.y*=alpha; acc.z*=alpha; acc.w*=alpha;
                #pragma unroll
                for (int kk=0; kk<16; kk++){
                    float p = s[kk];
                    float4 vv = ((const float4*)&Vsm[c*16+kk][0])[d];
                    acc.x += p*vv.x; acc.y += p*vv.y; acc.z += p*vv.z; acc.w += p*vv.w;
                }
                o4[d] = acc;
            }
        }
        __syncthreads();
    }

    float inv = 1.f / l;
    size_t base = (size_t)(b*TT + qt)*DD + h*DH;
    __nv_bfloat162* hp = (__nv_bfloat162*)(g_ctxh + base);
    __nv_bfloat162* lp = (__nv_bfloat162*)(g_ctxl + base);
    #pragma unroll
    for (int d=0; d<16; d++){
        float4 ov = o4[d];
        ov.x*=inv; ov.y*=inv; ov.z*=inv; ov.w*=inv;
        __nv_bfloat16 hx=__float2bfloat16_rn(ov.x), hy=__float2bfloat16_rn(ov.y);
        __nv_bfloat16 hz=__float2bfloat16_rn(ov.z), hw=__float2bfloat16_rn(ov.w);
        __nv_bfloat16 lx=__float2bfloat16_rn(ov.x-__bfloat162float(hx));
        __nv_bfloat16 ly=__float2bfloat16_rn(ov.y-__bfloat162float(hy));
        __nv_bfloat16 lz=__float2bfloat16_rn(ov.z-__bfloat162float(hz));
        __nv_bfloat16 lw=__float2bfloat16_rn(ov.w-__bfloat162float(hw));
        hp[d*2  ] = __halves2bfloat162(hx, hy);
        hp[d*2+1] = __halves2bfloat162(hz, hw);
        lp[d*2  ] = __halves2bfloat162(lx, ly);
        lp[d*2+1] = __halves2bfloat162(lz, lw);
    }
}

// ---------------- launch ----------------
extern "C" void kernel_launch(void* const* d_in, const int* in_sizes, int n_in,
                              void* d_out, int out_size) {
    const float* x      = (const float*)d_in[0];
    const float* w_qkv  = (const float*)d_in[1];
    const float* b_qkv  = (const float*)d_in[2];
    const float* w1w    = (const float*)d_in[3];
    const float* w2w    = (const float*)d_in[4];
    const float* w1r    = (const float*)d_in[5];
    const float* w2r    = (const float*)d_in[6];
    const float* w_out  = (const float*)d_in[7];
    const float* b_out  = (const float*)d_in[8];
    const float* dl     = (const float*)d_in[9];
    const float* bs     = (const float*)d_in[10];
    float* out = (float*)d_out;

    cudaFuncSetAttribute(k_mmagemm, cudaFuncAttributeMaxDynamicSharedMemorySize, GSM_TOT);

    // split-bf16 conversions
    k_conv<<<(M_TOT*DD/4 + 255)/256, 256>>>(x,     M_TOT*DD/4, 0, 0);
    k_conv<<<(3*DD*DD/4 + 255)/256, 256>>>(w_qkv, 3*DD*DD/4, 1, 0);
    k_conv<<<(64*DD/4 + 255)/256, 256>>>(w1w, 64*DD/4, 2, 0*(64*DD/4));
    k_conv<<<(64*DD/4 + 255)/256, 256>>>(w2w, 64*DD/4, 2, 1*(64*DD/4));
    k_conv<<<(64*DD/4 + 255)/256, 256>>>(w1r, 64*DD/4, 2, 2*(64*DD/4));
    k_conv<<<(64*DD/4 + 255)/256, 256>>>(w2r, 64*DD/4, 2, 3*(64*DD/4));
    k_conv<<<(DD*DD/4 + 255)/256, 256>>>(w_out, DD*DD/4, 3, 0);

    // tensor-core GEMMs (mma.sync path; tcgen05 is not reachable from compute_103 PTX)
    k_mmagemm<<<dim3(24, 32), 256, GSM_TOT>>>(0, b_qkv, nullptr);   // qkv -> g_qkv
    k_mmagemm<<<dim3(2, 32), 256, GSM_TOT>>>(1, nullptr, nullptr);  // line proj -> g_proj

    k_tables<<<(HH*TT + 255)/256, 256>>>(dl);
    k_lines<<<(M_TOT*HH + 255)/256, 256>>>();
    k_flash<<<dim3(TT/128, HH, BB), 128>>>(bs);

    k_mmagemm<<<dim3(8, 32), 256, GSM_TOT>>>(2, b_out, out);        // out proj -> d_out
}